// round 3
// baseline (speedup 1.0000x reference)
#include <cuda_runtime.h>
#include <math.h>

#define FDIM 256
#define BMAX 1024
#define MMAX 500000

// Scratch (allocation-free: __device__ globals)
__device__ float    g_groot[BMAX * FDIM];   // per-root x_r * w_ego_root * w_ego_u
__device__ float    g_nr[BMAX];             // ||x_r * w_ego_root||
__device__ float    g_sv[BMAX];             // x_r . w_layer_v
__device__ float    g_bf[BMAX];             // budgets / 200
__device__ unsigned g_pnorm[BMAX];          // encoded float max
__device__ float    g_agg[MMAX];            // segment_sum(sv[edge_src] -> edge_dst)
__device__ float    g_pu[MMAX];             // p_u before normalization

__device__ __forceinline__ unsigned f2key(float f) {
    unsigned u = __float_as_uint(f);
    return (u & 0x80000000u) ? ~u : (u | 0x80000000u);
}
__device__ __forceinline__ float key2f(unsigned k) {
    unsigned u = (k & 0x80000000u) ? (k ^ 0x80000000u) : ~k;
    return __uint_as_float(u);
}
__device__ __forceinline__ float dot4(float4 a, float4 b) {
    return a.x * b.x + a.y * b.y + a.z * b.z + a.w * b.w;
}
__device__ __forceinline__ float sq8(float4 a, float4 b, float4 wa, float4 wb) {
    float x0 = a.x*wa.x, x1 = a.y*wa.y, x2 = a.z*wa.z, x3 = a.w*wa.w;
    float y0 = b.x*wb.x, y1 = b.y*wb.y, y2 = b.z*wb.z, y3 = b.w*wb.w;
    return x0*x0 + x1*x1 + x2*x2 + x3*x3 + y0*y0 + y1*y1 + y2*y2 + y3*y3;
}

// K1: per-root precompute. One block (256 threads) per root.
__global__ void k_root(const float* __restrict__ x,
                       const float* __restrict__ w_ego_root,
                       const float* __restrict__ w_ego_u,
                       const float* __restrict__ w_layer_v,
                       const float* __restrict__ budgets,
                       const int*   __restrict__ batch_nodes)
{
    int b = blockIdx.x;
    int f = threadIdx.x;
    float xr = x[(size_t)batch_nodes[b] * FDIM + f];
    float h  = xr * w_ego_root[f];
    g_groot[b * FDIM + f] = h * w_ego_u[f];
    float s1 = h * h;
    float s2 = xr * w_layer_v[f];

    __shared__ float sh1[8], sh2[8];
    #pragma unroll
    for (int o = 16; o; o >>= 1) {
        s1 += __shfl_xor_sync(0xffffffffu, s1, o);
        s2 += __shfl_xor_sync(0xffffffffu, s2, o);
    }
    int w = f >> 5, l = f & 31;
    if (l == 0) { sh1[w] = s1; sh2[w] = s2; }
    __syncthreads();
    if (f == 0) {
        float t1 = 0.f, t2 = 0.f;
        #pragma unroll
        for (int i = 0; i < 8; i++) { t1 += sh1[i]; t2 += sh2[i]; }
        g_nr[b] = sqrtf(t1);
        g_sv[b] = t2;
        g_bf[b] = budgets[b] * (1.0f / 200.0f);
        g_pnorm[b] = f2key(-INFINITY);
    }
}

// K2: zero agg (vectorized)
__global__ void k_zero(int M)
{
    int i4 = (blockIdx.x * blockDim.x + threadIdx.x) * 4;
    if (i4 + 3 < M) {
        *(float4*)(g_agg + i4) = make_float4(0.f, 0.f, 0.f, 0.f);
    } else {
        for (int j = i4; j < M; j++) g_agg[j] = 0.0f;
    }
}

// K3: edge scatter-add (4 edges per thread)
__global__ void k_edge(const int* __restrict__ edge_src,
                       const int* __restrict__ edge_dst, int E)
{
    int i = (blockIdx.x * blockDim.x + threadIdx.x) * 4;
    if (i + 3 < E) {
        int4 s = *(const int4*)(edge_src + i);
        int4 d = *(const int4*)(edge_dst + i);
        atomicAdd(&g_agg[d.x], g_sv[s.x]);
        atomicAdd(&g_agg[d.y], g_sv[s.y]);
        atomicAdd(&g_agg[d.z], g_sv[s.z]);
        atomicAdd(&g_agg[d.w], g_sv[s.w]);
    } else {
        for (int j = i; j < E; j++)
            atomicAdd(&g_agg[edge_dst[j]], g_sv[edge_src[j]]);
    }
}

// K4: 4 candidates per warp; g_groot row shared when batch is uniform
// (batch_ptr is sorted, avg run length ~488, so uniform is the common case).
__global__ void __launch_bounds__(256)
k_cand(const float* __restrict__ x,
       const float* __restrict__ w_ego_u,
       const float* __restrict__ w_layer_u,
       const float* __restrict__ n_imp,
       const int*   __restrict__ u_ids,
       const int*   __restrict__ batch_ptr, int M)
{
    int t = threadIdx.x;
    int warp = t >> 5, lane = t & 31;
    int m0 = blockIdx.x * 32 + warp * 4;
    if (m0 >= M) return;

    const float4* x4 = (const float4*)x;
    const float4* g4 = (const float4*)g_groot;

    // per-lane weight slices (L1-hot)
    float4 wea = __ldg(((const float4*)w_ego_u)   + lane);
    float4 web = __ldg(((const float4*)w_ego_u)   + lane + 32);
    float4 wla = __ldg(((const float4*)w_layer_u) + lane);
    float4 wlb = __ldg(((const float4*)w_layer_u) + lane + 32);

    if (m0 + 3 < M) {
        int4 uu = *(const int4*)(u_ids + m0);      // m0 % 4 == 0
        int4 bb = *(const int4*)(batch_ptr + m0);

        // x rows for 4 candidates (8 wide loads, issued back-to-back)
        float4 xa0 = __ldg(x4 + (size_t)uu.x * 64 + lane);
        float4 xb0 = __ldg(x4 + (size_t)uu.x * 64 + lane + 32);
        float4 xa1 = __ldg(x4 + (size_t)uu.y * 64 + lane);
        float4 xb1 = __ldg(x4 + (size_t)uu.y * 64 + lane + 32);
        float4 xa2 = __ldg(x4 + (size_t)uu.z * 64 + lane);
        float4 xb2 = __ldg(x4 + (size_t)uu.z * 64 + lane + 32);
        float4 xa3 = __ldg(x4 + (size_t)uu.w * 64 + lane);
        float4 xb3 = __ldg(x4 + (size_t)uu.w * 64 + lane + 32);

        float dot0, dot1, dot2, dot3;
        bool uni = (bb.x == bb.w) && (bb.x == bb.y) && (bb.x == bb.z);
        if (uni) {
            float4 ga = __ldg(g4 + (size_t)bb.x * 64 + lane);
            float4 gb = __ldg(g4 + (size_t)bb.x * 64 + lane + 32);
            dot0 = dot4(xa0, ga) + dot4(xb0, gb);
            dot1 = dot4(xa1, ga) + dot4(xb1, gb);
            dot2 = dot4(xa2, ga) + dot4(xb2, gb);
            dot3 = dot4(xa3, ga) + dot4(xb3, gb);
        } else {
            float4 ga0 = __ldg(g4 + (size_t)bb.x * 64 + lane);
            float4 gb0 = __ldg(g4 + (size_t)bb.x * 64 + lane + 32);
            float4 ga1 = __ldg(g4 + (size_t)bb.y * 64 + lane);
            float4 gb1 = __ldg(g4 + (size_t)bb.y * 64 + lane + 32);
            float4 ga2 = __ldg(g4 + (size_t)bb.z * 64 + lane);
            float4 gb2 = __ldg(g4 + (size_t)bb.z * 64 + lane + 32);
            float4 ga3 = __ldg(g4 + (size_t)bb.w * 64 + lane);
            float4 gb3 = __ldg(g4 + (size_t)bb.w * 64 + lane + 32);
            dot0 = dot4(xa0, ga0) + dot4(xb0, gb0);
            dot1 = dot4(xa1, ga1) + dot4(xb1, gb1);
            dot2 = dot4(xa2, ga2) + dot4(xb2, gb2);
            dot3 = dot4(xa3, ga3) + dot4(xb3, gb3);
        }

        float nu0 = sq8(xa0, xb0, wea, web);
        float nu1 = sq8(xa1, xb1, wea, web);
        float nu2 = sq8(xa2, xb2, wea, web);
        float nu3 = sq8(xa3, xb3, wea, web);
        float su0 = dot4(xa0, wla) + dot4(xb0, wlb);
        float su1 = dot4(xa1, wla) + dot4(xb1, wlb);
        float su2 = dot4(xa2, wla) + dot4(xb2, wlb);
        float su3 = dot4(xa3, wla) + dot4(xb3, wlb);

        // ---- folded tree reduction: 12 sums in 27 shuffles ----
        dot0 += __shfl_xor_sync(0xffffffffu, dot0, 16);
        dot1 += __shfl_xor_sync(0xffffffffu, dot1, 16);
        dot2 += __shfl_xor_sync(0xffffffffu, dot2, 16);
        dot3 += __shfl_xor_sync(0xffffffffu, dot3, 16);
        nu0  += __shfl_xor_sync(0xffffffffu, nu0,  16);
        nu1  += __shfl_xor_sync(0xffffffffu, nu1,  16);
        nu2  += __shfl_xor_sync(0xffffffffu, nu2,  16);
        nu3  += __shfl_xor_sync(0xffffffffu, nu3,  16);
        su0  += __shfl_xor_sync(0xffffffffu, su0,  16);
        su1  += __shfl_xor_sync(0xffffffffu, su1,  16);
        su2  += __shfl_xor_sync(0xffffffffu, su2,  16);
        su3  += __shfl_xor_sync(0xffffffffu, su3,  16);

        bool hi16 = (lane & 16) != 0;
        float dA = hi16 ? dot1 : dot0;   // lanes0-15: cand0, lanes16-31: cand1
        float dB = hi16 ? dot3 : dot2;   // lanes0-15: cand2, lanes16-31: cand3
        float nA = hi16 ? nu1 : nu0;
        float nB = hi16 ? nu3 : nu2;
        float sA = hi16 ? su1 : su0;
        float sB = hi16 ? su3 : su2;

        dA += __shfl_xor_sync(0xffffffffu, dA, 8);
        dB += __shfl_xor_sync(0xffffffffu, dB, 8);
        nA += __shfl_xor_sync(0xffffffffu, nA, 8);
        nB += __shfl_xor_sync(0xffffffffu, nB, 8);
        sA += __shfl_xor_sync(0xffffffffu, sA, 8);
        sB += __shfl_xor_sync(0xffffffffu, sB, 8);

        bool hi8 = (lane & 8) != 0;
        float d = hi8 ? dB : dA;   // groups: l0-7:c0, l8-15:c2, l16-23:c1, l24-31:c3
        float n = hi8 ? nB : nA;
        float s = hi8 ? sB : sA;

        #pragma unroll
        for (int o = 4; o; o >>= 1) {
            d += __shfl_xor_sync(0xffffffffu, d, o);
            n += __shfl_xor_sync(0xffffffffu, n, o);
            s += __shfl_xor_sync(0xffffffffu, s, o);
        }

        // finalize on lanes 0, 8, 16, 24
        if ((lane & 7) == 0) {
            int ci = ((lane >> 3) & 1) * 2 + ((lane >> 4) & 1);
            int m  = m0 + ci;
            int u  = (ci == 0) ? uu.x : (ci == 1) ? uu.y : (ci == 2) ? uu.z : uu.w;
            int b  = (ci == 0) ? bb.x : (ci == 1) ? bb.y : (ci == 2) ? bb.z : bb.w;
            float nr = fmaxf(g_nr[b], 1e-6f);
            float bf = g_bf[b];
            float ni = __ldg(n_imp + u);
            float ag = g_agg[m];
            float ego = d / (nr * fmaxf(sqrtf(n), 1e-6f));
            float p = (0.5f * ego + 0.5f * tanhf(ag + s)) * ni * bf;
            g_pu[m] = p;
            atomicMax(&g_pnorm[b], f2key(p));
        }
    } else {
        // tail: one candidate at a time, plain 5-round reduction
        for (int m = m0; m < M; m++) {
            int u = __ldg(u_ids + m);
            int b = __ldg(batch_ptr + m);
            float4 xa = __ldg(x4 + (size_t)u * 64 + lane);
            float4 xb = __ldg(x4 + (size_t)u * 64 + lane + 32);
            float4 ga = __ldg(g4 + (size_t)b * 64 + lane);
            float4 gb = __ldg(g4 + (size_t)b * 64 + lane + 32);
            float d = dot4(xa, ga) + dot4(xb, gb);
            float n = sq8(xa, xb, wea, web);
            float s = dot4(xa, wla) + dot4(xb, wlb);
            #pragma unroll
            for (int o = 16; o; o >>= 1) {
                d += __shfl_xor_sync(0xffffffffu, d, o);
                n += __shfl_xor_sync(0xffffffffu, n, o);
                s += __shfl_xor_sync(0xffffffffu, s, o);
            }
            if (lane == 0) {
                float nr = fmaxf(g_nr[b], 1e-6f);
                float ego = d / (nr * fmaxf(sqrtf(n), 1e-6f));
                float p = (0.5f * ego + 0.5f * tanhf(g_agg[m] + s))
                          * __ldg(n_imp + u) * g_bf[b];
                g_pu[m] = p;
                atomicMax(&g_pnorm[b], f2key(p));
            }
        }
    }
}

// K5: normalize + nan/inf replace + clip (vectorized)
__global__ void k_final(const int* __restrict__ batch_ptr,
                        float* __restrict__ out, int M)
{
    int m = (blockIdx.x * blockDim.x + threadIdx.x) * 4;
    if (m + 3 < M) {
        int4   bp = *(const int4*)(batch_ptr + m);
        float4 pu = *(const float4*)(g_pu + m);
        float4 r;
        {
            float p = pu.x / key2f(g_pnorm[bp.x]) + 1.0f;
            if (isnan(p)) p = 0.0f; else if (isinf(p)) p = 1.0f;
            r.x = fminf(fmaxf(p, 1e-5f), 1.0f);
        }
        {
            float p = pu.y / key2f(g_pnorm[bp.y]) + 1.0f;
            if (isnan(p)) p = 0.0f; else if (isinf(p)) p = 1.0f;
            r.y = fminf(fmaxf(p, 1e-5f), 1.0f);
        }
        {
            float p = pu.z / key2f(g_pnorm[bp.z]) + 1.0f;
            if (isnan(p)) p = 0.0f; else if (isinf(p)) p = 1.0f;
            r.z = fminf(fmaxf(p, 1e-5f), 1.0f);
        }
        {
            float p = pu.w / key2f(g_pnorm[bp.w]) + 1.0f;
            if (isnan(p)) p = 0.0f; else if (isinf(p)) p = 1.0f;
            r.w = fminf(fmaxf(p, 1e-5f), 1.0f);
        }
        *(float4*)(out + m) = r;
    } else {
        for (int j = m; j < M; j++) {
            float p = g_pu[j] / key2f(g_pnorm[batch_ptr[j]]) + 1.0f;
            if (isnan(p)) p = 0.0f; else if (isinf(p)) p = 1.0f;
            out[j] = fminf(fmaxf(p, 1e-5f), 1.0f);
        }
    }
}

extern "C" void kernel_launch(void* const* d_in, const int* in_sizes, int n_in,
                              void* d_out, int out_size)
{
    const float* x           = (const float*)d_in[0];
    const float* w_ego_root  = (const float*)d_in[1];
    const float* w_ego_u     = (const float*)d_in[2];
    const float* w_layer_v   = (const float*)d_in[3];
    const float* w_layer_u   = (const float*)d_in[4];
    const float* n_imp       = (const float*)d_in[5];
    const float* budgets     = (const float*)d_in[6];
    const int*   batch_nodes = (const int*)d_in[7];
    const int*   u_ids       = (const int*)d_in[8];
    const int*   batch_ptr   = (const int*)d_in[9];
    const int*   edge_src    = (const int*)d_in[10];
    const int*   edge_dst    = (const int*)d_in[11];
    float* out = (float*)d_out;

    int B = in_sizes[7];
    int M = in_sizes[8];
    int E = in_sizes[10];

    k_root<<<B, FDIM>>>(x, w_ego_root, w_ego_u, w_layer_v, budgets, batch_nodes);
    k_zero<<<(M / 4 + 255) / 256, 256>>>(M);
    k_edge<<<(E / 4 + 255) / 256, 256>>>(edge_src, edge_dst, E);
    k_cand<<<(M + 31) / 32, 256>>>(x, w_ego_u, w_layer_u, n_imp, u_ids, batch_ptr, M);
    k_final<<<(M / 4 + 255) / 256, 256>>>(batch_ptr, out, M);
}

// round 4
// speedup vs baseline: 1.7543x; 1.7543x over previous
#include <cuda_runtime.h>
#include <math.h>

#define FDIM 256
#define BMAX 1024
#define MMAX 500000

// Scratch (allocation-free: __device__ globals)
__device__ float    g_groot[BMAX * FDIM];   // per-root x_r * w_ego_root * w_ego_u
__device__ float2   g_rootsc[BMAX];         // {nr, budgets/200}
__device__ float    g_sv[BMAX];             // x_r . w_layer_v
__device__ unsigned g_pnorm[BMAX];          // encoded float max
__device__ float    g_agg[MMAX];            // segment_sum(sv[edge_src] -> edge_dst)
__device__ float    g_pu[MMAX];             // p_u before normalization

__device__ __forceinline__ unsigned f2key(float f) {
    unsigned u = __float_as_uint(f);
    return (u & 0x80000000u) ? ~u : (u | 0x80000000u);
}
__device__ __forceinline__ float key2f(unsigned k) {
    unsigned u = (k & 0x80000000u) ? (k ^ 0x80000000u) : ~k;
    return __uint_as_float(u);
}
__device__ __forceinline__ float dot4(float4 a, float4 b) {
    return a.x * b.x + a.y * b.y + a.z * b.z + a.w * b.w;
}
__device__ __forceinline__ float sq8(float4 a, float4 b, float4 wa, float4 wb) {
    float x0 = a.x*wa.x, x1 = a.y*wa.y, x2 = a.z*wa.z, x3 = a.w*wa.w;
    float y0 = b.x*wb.x, y1 = b.y*wb.y, y2 = b.z*wb.z, y3 = b.w*wb.w;
    return x0*x0 + x1*x1 + x2*x2 + x3*x3 + y0*y0 + y1*y1 + y2*y2 + y3*y3;
}

// K1: per-root precompute (one block per root) + zero g_agg (strided).
__global__ void k_root(const float* __restrict__ x,
                       const float* __restrict__ w_ego_root,
                       const float* __restrict__ w_ego_u,
                       const float* __restrict__ w_layer_v,
                       const float* __restrict__ budgets,
                       const int*   __restrict__ batch_nodes,
                       int B, int M)
{
    int b = blockIdx.x;
    int f = threadIdx.x;

    // fused: zero the segment-sum buffer
    for (int j = b * FDIM + f; j < M; j += gridDim.x * FDIM) g_agg[j] = 0.0f;

    float xr = x[(size_t)batch_nodes[b] * FDIM + f];
    float h  = xr * w_ego_root[f];
    g_groot[b * FDIM + f] = h * w_ego_u[f];
    float s1 = h * h;
    float s2 = xr * w_layer_v[f];

    __shared__ float sh1[8], sh2[8];
    #pragma unroll
    for (int o = 16; o; o >>= 1) {
        s1 += __shfl_xor_sync(0xffffffffu, s1, o);
        s2 += __shfl_xor_sync(0xffffffffu, s2, o);
    }
    int w = f >> 5, l = f & 31;
    if (l == 0) { sh1[w] = s1; sh2[w] = s2; }
    __syncthreads();
    if (f == 0) {
        float t1 = 0.f, t2 = 0.f;
        #pragma unroll
        for (int i = 0; i < 8; i++) { t1 += sh1[i]; t2 += sh2[i]; }
        g_rootsc[b] = make_float2(sqrtf(t1), budgets[b] * (1.0f / 200.0f));
        g_sv[b] = t2;
        g_pnorm[b] = f2key(-INFINITY);
    }
}

// K3: edge scatter-add (4 edges per thread)
__global__ void k_edge(const int* __restrict__ edge_src,
                       const int* __restrict__ edge_dst, int E)
{
    int i = (blockIdx.x * blockDim.x + threadIdx.x) * 4;
    if (i + 3 < E) {
        int4 s = *(const int4*)(edge_src + i);
        int4 d = *(const int4*)(edge_dst + i);
        atomicAdd(&g_agg[d.x], g_sv[s.x]);
        atomicAdd(&g_agg[d.y], g_sv[s.y]);
        atomicAdd(&g_agg[d.z], g_sv[s.z]);
        atomicAdd(&g_agg[d.w], g_sv[s.w]);
    } else {
        for (int j = i; j < E; j++)
            atomicAdd(&g_agg[edge_dst[j]], g_sv[edge_src[j]]);
    }
}

// K4: 2 candidates per warp-iteration, grid-stride over pairs.
// Weights persist in registers across iterations; g_groot row dedup'd when
// both candidates share a batch (sorted batch_ptr -> ~99.8% of pairs).
__global__ void __launch_bounds__(256)
k_cand(const float* __restrict__ x,
       const float* __restrict__ w_ego_u,
       const float* __restrict__ w_layer_u,
       const float* __restrict__ n_imp,
       const int*   __restrict__ u_ids,
       const int*   __restrict__ batch_ptr, int M)
{
    int lane  = threadIdx.x & 31;
    int gwarp = (blockIdx.x * blockDim.x + threadIdx.x) >> 5;
    int nwarps = gridDim.x * (blockDim.x >> 5);

    const float4* x4 = (const float4*)x;
    const float4* g4 = (const float4*)g_groot;

    // weights live in registers for the whole loop (L1-hot loads, done once)
    float4 wea = __ldg(((const float4*)w_ego_u)   + lane);
    float4 web = __ldg(((const float4*)w_ego_u)   + lane + 32);
    float4 wla = __ldg(((const float4*)w_layer_u) + lane);
    float4 wlb = __ldg(((const float4*)w_layer_u) + lane + 32);

    // odd-M tail: one designated warp handles the last candidate solo
    if ((M & 1) && gwarp == 0) {
        int m = M - 1;
        int u = __ldg(u_ids + m);
        int b = __ldg(batch_ptr + m);
        float4 xa = __ldg(x4 + (size_t)u * 64 + lane);
        float4 xb = __ldg(x4 + (size_t)u * 64 + lane + 32);
        float4 ga = __ldg(g4 + (size_t)b * 64 + lane);
        float4 gb = __ldg(g4 + (size_t)b * 64 + lane + 32);
        float d = dot4(xa, ga) + dot4(xb, gb);
        float n = sq8(xa, xb, wea, web);
        float s = dot4(xa, wla) + dot4(xb, wlb);
        #pragma unroll
        for (int o = 16; o; o >>= 1) {
            d += __shfl_xor_sync(0xffffffffu, d, o);
            n += __shfl_xor_sync(0xffffffffu, n, o);
            s += __shfl_xor_sync(0xffffffffu, s, o);
        }
        if (lane == 0) {
            float2 sc = __ldg(g_rootsc + b);
            float ego = d / (fmaxf(sc.x, 1e-6f) * fmaxf(sqrtf(n), 1e-6f));
            float p = (0.5f * ego + 0.5f * tanhf(g_agg[m] + s))
                      * __ldg(n_imp + u) * sc.y;
            g_pu[m] = p;
            atomicMax(&g_pnorm[b], f2key(p));
        }
    }

    int npairs = M >> 1;
    for (int p = gwarp; p < npairs; p += nwarps) {
        int m0 = p * 2;
        int2 uu = *(const int2*)(u_ids + m0);      // warp-uniform broadcast
        int2 bb = *(const int2*)(batch_ptr + m0);

        float4 xa0 = __ldg(x4 + (size_t)uu.x * 64 + lane);
        float4 xb0 = __ldg(x4 + (size_t)uu.x * 64 + lane + 32);
        float4 xa1 = __ldg(x4 + (size_t)uu.y * 64 + lane);
        float4 xb1 = __ldg(x4 + (size_t)uu.y * 64 + lane + 32);
        float4 ga  = __ldg(g4 + (size_t)bb.x * 64 + lane);
        float4 gb  = __ldg(g4 + (size_t)bb.x * 64 + lane + 32);

        float dot0 = dot4(xa0, ga) + dot4(xb0, gb);
        float dot1;
        if (bb.y == bb.x) {                        // warp-uniform branch
            dot1 = dot4(xa1, ga) + dot4(xb1, gb);
        } else {
            float4 ga1 = __ldg(g4 + (size_t)bb.y * 64 + lane);
            float4 gb1 = __ldg(g4 + (size_t)bb.y * 64 + lane + 32);
            dot1 = dot4(xa1, ga1) + dot4(xb1, gb1);
        }

        float nu0 = sq8(xa0, xb0, wea, web);
        float nu1 = sq8(xa1, xb1, wea, web);
        float su0 = dot4(xa0, wla) + dot4(xb0, wlb);
        float su1 = dot4(xa1, wla) + dot4(xb1, wlb);

        // folded reduction: 6 sums in 18 shuffles
        dot0 += __shfl_xor_sync(0xffffffffu, dot0, 16);
        dot1 += __shfl_xor_sync(0xffffffffu, dot1, 16);
        nu0  += __shfl_xor_sync(0xffffffffu, nu0,  16);
        nu1  += __shfl_xor_sync(0xffffffffu, nu1,  16);
        su0  += __shfl_xor_sync(0xffffffffu, su0,  16);
        su1  += __shfl_xor_sync(0xffffffffu, su1,  16);

        bool hi16 = (lane & 16) != 0;
        float d = hi16 ? dot1 : dot0;
        float n = hi16 ? nu1  : nu0;
        float s = hi16 ? su1  : su0;
        #pragma unroll
        for (int o = 8; o; o >>= 1) {
            d += __shfl_xor_sync(0xffffffffu, d, o);
            n += __shfl_xor_sync(0xffffffffu, n, o);
            s += __shfl_xor_sync(0xffffffffu, s, o);
        }
        // lanes 0 and 16 hold the two candidates' full sums

        if ((lane & 15) == 0) {
            bool second = lane != 0;
            int m = second ? m0 + 1 : m0;
            int u = second ? uu.y : uu.x;
            int b = second ? bb.y : bb.x;
            float2 sc = __ldg(g_rootsc + b);       // {nr, bf}
            float ni = __ldg(n_imp + u);
            float ag = g_agg[m];
            float ego = d / (fmaxf(sc.x, 1e-6f) * fmaxf(sqrtf(n), 1e-6f));
            float pv = (0.5f * ego + 0.5f * tanhf(ag + s)) * ni * sc.y;
            g_pu[m] = pv;
            atomicMax(&g_pnorm[b], f2key(pv));
        }
    }
}

// K5: normalize + nan/inf replace + clip (vectorized)
__global__ void k_final(const int* __restrict__ batch_ptr,
                        float* __restrict__ out, int M)
{
    int m = (blockIdx.x * blockDim.x + threadIdx.x) * 4;
    if (m + 3 < M) {
        int4   bp = *(const int4*)(batch_ptr + m);
        float4 pu = *(const float4*)(g_pu + m);
        float4 r;
        {
            float p = pu.x / key2f(g_pnorm[bp.x]) + 1.0f;
            if (isnan(p)) p = 0.0f; else if (isinf(p)) p = 1.0f;
            r.x = fminf(fmaxf(p, 1e-5f), 1.0f);
        }
        {
            float p = pu.y / key2f(g_pnorm[bp.y]) + 1.0f;
            if (isnan(p)) p = 0.0f; else if (isinf(p)) p = 1.0f;
            r.y = fminf(fmaxf(p, 1e-5f), 1.0f);
        }
        {
            float p = pu.z / key2f(g_pnorm[bp.z]) + 1.0f;
            if (isnan(p)) p = 0.0f; else if (isinf(p)) p = 1.0f;
            r.z = fminf(fmaxf(p, 1e-5f), 1.0f);
        }
        {
            float p = pu.w / key2f(g_pnorm[bp.w]) + 1.0f;
            if (isnan(p)) p = 0.0f; else if (isinf(p)) p = 1.0f;
            r.w = fminf(fmaxf(p, 1e-5f), 1.0f);
        }
        *(float4*)(out + m) = r;
    } else {
        for (int j = m; j < M; j++) {
            float p = g_pu[j] / key2f(g_pnorm[batch_ptr[j]]) + 1.0f;
            if (isnan(p)) p = 0.0f; else if (isinf(p)) p = 1.0f;
            out[j] = fminf(fmaxf(p, 1e-5f), 1.0f);
        }
    }
}

extern "C" void kernel_launch(void* const* d_in, const int* in_sizes, int n_in,
                              void* d_out, int out_size)
{
    const float* x           = (const float*)d_in[0];
    const float* w_ego_root  = (const float*)d_in[1];
    const float* w_ego_u     = (const float*)d_in[2];
    const float* w_layer_v   = (const float*)d_in[3];
    const float* w_layer_u   = (const float*)d_in[4];
    const float* n_imp       = (const float*)d_in[5];
    const float* budgets     = (const float*)d_in[6];
    const int*   batch_nodes = (const int*)d_in[7];
    const int*   u_ids       = (const int*)d_in[8];
    const int*   batch_ptr   = (const int*)d_in[9];
    const int*   edge_src    = (const int*)d_in[10];
    const int*   edge_dst    = (const int*)d_in[11];
    float* out = (float*)d_out;

    int B = in_sizes[7];
    int M = in_sizes[8];
    int E = in_sizes[10];

    k_root<<<B, FDIM>>>(x, w_ego_root, w_ego_u, w_layer_v, budgets,
                        batch_nodes, B, M);
    k_edge<<<(E / 4 + 255) / 256, 256>>>(edge_src, edge_dst, E);

    // ~8 pairs per warp: grid-stride loop amortizes weight loads
    int npairs = M >> 1;
    int nblocks = (npairs + 8 * 8 - 1) / (8 * 8);   // 8 warps/block, 8 iters/warp
    if (nblocks < 1) nblocks = 1;
    k_cand<<<nblocks, 256>>>(x, w_ego_u, w_layer_u, n_imp, u_ids, batch_ptr, M);

    k_final<<<(M / 4 + 255) / 256, 256>>>(batch_ptr, out, M);
}